// round 2
// baseline (speedup 1.0000x reference)
#include <cuda_runtime.h>
#include <stdint.h>

// RecyclingEmbedder: out[i,j,:] = W[:,bin(d_ij)] + b  (or just b if no bin hit)
// d_ij = ||x_i - x_j||^2, bins = linspace(3.25,20.75,15)^2, strict open intervals.
//
// Store-bandwidth-bound: 1536*1536*128 fp32 = 1.208 GB of output stores.
// Strategy: 16x128 fp32 table (W[:,k]+b, plus b-only row) in shared, x (18KB) in
// shared. Each warp processes 32 consecutive (i,j) pairs: lanes compute the 32
// bin indices in parallel, then a tight 32-iteration stream loop does
// SHFL(idx) -> LDS.128(table row) -> STG.128, i.e. 16KB of contiguous,
// perfectly-coalesced output per warp-group.

#define N_PTS   1536
#define D_PAIR  128
#define GROUPS_PER_ROW (N_PTS / 32)          // 48
#define NGROUPS (N_PTS * GROUPS_PER_ROW)     // 73728
#define NWARPS_PER_BLOCK 8
#define BLOCK_THREADS (NWARPS_PER_BLOCK * 32)

__global__ __launch_bounds__(BLOCK_THREADS)
void recycling_embedder_kernel(const float* __restrict__ x,
                               const float* __restrict__ W,
                               const float* __restrict__ b,
                               float* __restrict__ out)
{
    __shared__ float s_table[16 * D_PAIR];   // 8 KB:  row k = W[:,k]+b, row 15 = b
    __shared__ float s_x[N_PTS * 3];         // 18 KB

    const int tid = threadIdx.x;

    // Build table: table[k][p] = W[p*15+k] + b[p] for k<15; table[15][p] = b[p].
    for (int idx = tid; idx < 16 * D_PAIR; idx += BLOCK_THREADS) {
        int k = idx >> 7;          // table row
        int p = idx & (D_PAIR - 1);
        float v = b[p];
        if (k < 15) v += W[p * 15 + k];
        s_table[idx] = v;
    }
    // Stage coordinates.
    for (int idx = tid; idx < N_PTS * 3; idx += BLOCK_THREADS) {
        s_x[idx] = x[idx];
    }
    __syncthreads();

    const int lane = tid & 31;
    const int warp = tid >> 5;
    const int gwarp  = blockIdx.x * NWARPS_PER_BLOCK + warp;
    const int nwarps = gridDim.x * NWARPS_PER_BLOCK;

    for (int g = gwarp; g < NGROUPS; g += nwarps) {
        const int i  = g / GROUPS_PER_ROW;
        const int j0 = (g - i * GROUPS_PER_ROW) * 32;
        const int j  = j0 + lane;

        // Phase 1: one pair per lane — squared distance + bin search.
        // Match reference rounding exactly: no FMA contraction, sum order
        // (dx^2 + dy^2) + dz^2.
        float dx = s_x[i * 3 + 0] - s_x[j * 3 + 0];
        float dy = s_x[i * 3 + 1] - s_x[j * 3 + 1];
        float dz = s_x[i * 3 + 2] - s_x[j * 3 + 2];
        float d  = __fadd_rn(__fadd_rn(__fmul_rn(dx, dx), __fmul_rn(dy, dy)),
                             __fmul_rn(dz, dz));

        int bi = 15;  // default: no bin hit -> b-only row
        #pragma unroll
        for (int k = 0; k < 15; k++) {
            const float e0 = 3.25f + 1.25f * (float)k;
            const float lo = e0 * e0;                       // compile-time folded
            const float e1 = 3.25f + 1.25f * (float)(k + 1);
            const float hi = (k == 14) ? 100000000.0f : e1 * e1;
            if (d > lo && d < hi) bi = k;
        }

        // Phase 2: stream 32 rows (16 KB contiguous) — SHFL + LDS.128 + STG.128.
        float4* dst = reinterpret_cast<float4*>(
                          out + ((size_t)i * N_PTS + j0) * D_PAIR) + lane;
        #pragma unroll
        for (int p = 0; p < 32; p++) {
            int bp = __shfl_sync(0xffffffffu, bi, p);
            float4 v = *reinterpret_cast<const float4*>(
                           &s_table[bp * D_PAIR + lane * 4]);
            dst[p * (D_PAIR / 4)] = v;   // STG.E.128, constant imm offsets
        }
    }
}

extern "C" void kernel_launch(void* const* d_in, const int* in_sizes, int n_in,
                              void* d_out, int out_size)
{
    const float* x = (const float*)d_in[0];   // [1536, 3]
    const float* W = (const float*)d_in[1];   // [128, 15]
    const float* b = (const float*)d_in[2];   // [128]
    float* out = (float*)d_out;               // [1536, 1536, 128]

    // 1184 blocks: enough waves to balance the grid-stride loop while keeping
    // the per-block smem init traffic (~26 KB * 1184 = 30 MB) negligible.
    recycling_embedder_kernel<<<1184, BLOCK_THREADS>>>(x, W, b, out);
}

// round 3
// speedup vs baseline: 1.3139x; 1.3139x over previous
#include <cuda_runtime.h>
#include <stdint.h>

// RecyclingEmbedder: out[i,j,:] = W[:,bin(d_ij)] + b  (or just b if no bin hit)
//
// R2 ncu: l1tex 76.5% binding, DRAM 55.7%. Cause: 1 LDS.128 per STG.128.
// Fix: bin index is warp-uniform after shfl, and the bin distribution is
// heavily skewed (d ~ 2*chi2_3: ~83% "no bin" -> b row, ~15% bin 0, ~2% rest).
// Keep rows 15 and 0 in registers; LDS only on the rare path. Stores use .cs
// (streaming) since output is write-once.

#define N_PTS   1536
#define D_PAIR  128
#define GROUPS_PER_ROW (N_PTS / 32)          // 48
#define NGROUPS (N_PTS * GROUPS_PER_ROW)     // 73728
#define NWARPS_PER_BLOCK 8
#define BLOCK_THREADS (NWARPS_PER_BLOCK * 32)

__global__ __launch_bounds__(BLOCK_THREADS)
void recycling_embedder_kernel(const float* __restrict__ x,
                               const float* __restrict__ W,
                               const float* __restrict__ b,
                               float* __restrict__ out)
{
    __shared__ float s_table[16 * D_PAIR];   // 8 KB:  row k = W[:,k]+b, row 15 = b
    __shared__ float s_x[N_PTS * 3];         // 18 KB

    const int tid = threadIdx.x;

    // Build table: table[k][p] = W[p*15+k] + b[p] for k<15; table[15][p] = b[p].
    for (int idx = tid; idx < 16 * D_PAIR; idx += BLOCK_THREADS) {
        int k = idx >> 7;
        int p = idx & (D_PAIR - 1);
        float v = b[p];
        if (k < 15) v += W[p * 15 + k];
        s_table[idx] = v;
    }
    for (int idx = tid; idx < N_PTS * 3; idx += BLOCK_THREADS) {
        s_x[idx] = x[idx];
    }
    __syncthreads();

    const int lane = tid & 31;
    const int warp = tid >> 5;
    const int gwarp  = blockIdx.x * NWARPS_PER_BLOCK + warp;
    const int nwarps = gridDim.x * NWARPS_PER_BLOCK;

    // Hot rows resident in registers: row 15 (b only, ~83%) and row 0 (~15%).
    const float4 v15 = *reinterpret_cast<const float4*>(&s_table[15 * D_PAIR + lane * 4]);
    const float4 v0  = *reinterpret_cast<const float4*>(&s_table[ 0 * D_PAIR + lane * 4]);

    for (int g = gwarp; g < NGROUPS; g += nwarps) {
        const int i  = g / GROUPS_PER_ROW;
        const int j0 = (g - i * GROUPS_PER_ROW) * 32;
        const int j  = j0 + lane;

        // Phase 1: one pair per lane. Match reference rounding exactly:
        // no FMA contraction, sum order (dx^2 + dy^2) + dz^2.
        float dx = s_x[i * 3 + 0] - s_x[j * 3 + 0];
        float dy = s_x[i * 3 + 1] - s_x[j * 3 + 1];
        float dz = s_x[i * 3 + 2] - s_x[j * 3 + 2];
        float d  = __fadd_rn(__fadd_rn(__fmul_rn(dx, dx), __fmul_rn(dy, dy)),
                             __fmul_rn(dz, dz));

        int bi = 15;  // default: no bin hit -> b-only row
        #pragma unroll
        for (int k = 0; k < 15; k++) {
            const float e0 = 3.25f + 1.25f * (float)k;
            const float lo = e0 * e0;                       // folded at compile time
            const float e1 = 3.25f + 1.25f * (float)(k + 1);
            const float hi = (k == 14) ? 100000000.0f : e1 * e1;
            if (d > lo && d < hi) bi = k;
        }

        // Phase 2: stream 32 rows (16 KB contiguous). bp is warp-uniform, so
        // the branch is divergence-free; LDS only on the ~2% rare path.
        float4* dst = reinterpret_cast<float4*>(
                          out + ((size_t)i * N_PTS + j0) * D_PAIR) + lane;
        #pragma unroll
        for (int p = 0; p < 32; p++) {
            int bp = __shfl_sync(0xffffffffu, bi, p);
            float4 v;
            if (bp == 15)      v = v15;
            else if (bp == 0)  v = v0;
            else               v = *reinterpret_cast<const float4*>(
                                       &s_table[bp * D_PAIR + lane * 4]);
            __stcs(&dst[p * (D_PAIR / 4)], v);   // STG.E.128 streaming
        }
    }
}

extern "C" void kernel_launch(void* const* d_in, const int* in_sizes, int n_in,
                              void* d_out, int out_size)
{
    const float* x = (const float*)d_in[0];   // [1536, 3]
    const float* W = (const float*)d_in[1];   // [128, 15]
    const float* b = (const float*)d_in[2];   // [128]
    float* out = (float*)d_out;               // [1536, 1536, 128]

    recycling_embedder_kernel<<<1184, BLOCK_THREADS>>>(x, W, b, out);
}